// round 2
// baseline (speedup 1.0000x reference)
#include <cuda_runtime.h>
#include <math.h>
#include <stdint.h>

#define NV 100000
#define NE 20000
#define NNZ_C 3200000
#define CH 128
#define NCLS 40
#define BN_EPS 1e-5f

// ---------------- scratch (device globals; no cudaMalloc allowed) ----------------
__device__ static float g_ebuf [(size_t)NE * CH];    // 10.24 MB
__device__ static float g_ebuf2[(size_t)NE * CH];    // 10.24 MB
__device__ static float g_vbuf [(size_t)NV * CH];    // 51.2 MB
__device__ static float g_vbuf2[(size_t)NV * NCLS];  // 16 MB
__device__ static int   g_eptr[NE + 1];
__device__ static int   g_vptr[NV + 1];
__device__ static int   g_efill[NE];
__device__ static int   g_vfill[NV];
__device__ static int   g_eadj[NNZ_C];               // 12.8 MB
__device__ static int   g_vadj[NNZ_C];               // 12.8 MB

// ---------------- CSR build ----------------
__global__ void zero_counts(int* e, int ne1, int* v, int nv1) {
    int total = ne1 + nv1;
    for (int i = blockIdx.x * blockDim.x + threadIdx.x; i < total; i += gridDim.x * blockDim.x) {
        if (i < ne1) e[i] = 0; else v[i - ne1] = 0;
    }
}

__global__ void hist_kernel(const int* __restrict__ v_ids, const int* __restrict__ e_ids,
                            int* e_cnt, int* v_cnt, int nnz) {
    for (int i = blockIdx.x * blockDim.x + threadIdx.x; i < nnz; i += gridDim.x * blockDim.x) {
        atomicAdd(&e_cnt[e_ids[i] + 1], 1);
        atomicAdd(&v_cnt[v_ids[i] + 1], 1);
    }
}

// 2 blocks: block 0 scans e_ptr, block 1 scans v_ptr (inclusive, in place).
__global__ void scan_two(int* e, int ne, int* v, int nv) {
    int* a; int n;
    if (blockIdx.x == 0) { a = e; n = ne; } else { a = v; n = nv; }
    __shared__ int wsum[32];
    __shared__ int blktot;
    const int tid = threadIdx.x;
    const int lane = tid & 31, warp = tid >> 5;
    int carry = 0;
    for (int base = 0; base < n; base += 1024) {
        int i = base + tid;
        int x = (i < n) ? a[i] : 0;
        int s = x;
        #pragma unroll
        for (int d = 1; d < 32; d <<= 1) {
            int t = __shfl_up_sync(0xffffffffu, s, d);
            if (lane >= d) s += t;
        }
        if (lane == 31) wsum[warp] = s;
        __syncthreads();
        if (warp == 0) {
            int ws = wsum[lane];
            #pragma unroll
            for (int d = 1; d < 32; d <<= 1) {
                int t = __shfl_up_sync(0xffffffffu, ws, d);
                if (lane >= d) ws += t;
            }
            wsum[lane] = ws;
            if (lane == 31) blktot = ws;
        }
        __syncthreads();
        int off = (warp > 0) ? wsum[warp - 1] : 0;
        s += off + carry;
        if (i < n) a[i] = s;
        carry += blktot;
        __syncthreads();
    }
}

__global__ void init_fill(const int* eptr, int* efill, int ne,
                          const int* vptr, int* vfill, int nv) {
    int total = ne + nv;
    for (int i = blockIdx.x * blockDim.x + threadIdx.x; i < total; i += gridDim.x * blockDim.x) {
        if (i < ne) efill[i] = eptr[i];
        else        vfill[i - ne] = vptr[i - ne];
    }
}

__global__ void build_adj(const int* __restrict__ v_ids, const int* __restrict__ e_ids,
                          int* efill, int* vfill, int* eadj, int* vadj, int nnz) {
    for (int i = blockIdx.x * blockDim.x + threadIdx.x; i < nnz; i += gridDim.x * blockDim.x) {
        int e = e_ids[i], v = v_ids[i];
        int pe = atomicAdd(&efill[e], 1);
        eadj[pe] = v;
        int pv = atomicAdd(&vfill[v], 1);
        vadj[pv] = e;
    }
}

// ---------------- segment mean (gather-reduce over CSR) ----------------
// EPI: 0 = none, 1 = relu, 2 = relu + batchnorm, 3 = log_softmax
template<int C, int NC4, int R, int EPI>
__global__ void __launch_bounds__(NC4 * R)
seg_agg(const float* __restrict__ src, const int* __restrict__ ptr,
        const int* __restrict__ adj, float* __restrict__ dst, int nseg,
        const float* __restrict__ bng, const float* __restrict__ bnb,
        const float* __restrict__ bnm, const float* __restrict__ bnv) {
    const int tid = threadIdx.x;
    const int chunk = tid % NC4;       // float4 chunk within a row
    const int rl = tid / NC4;          // row lane (rows in flight)
    __shared__ float4 sacc[R][NC4];
    __shared__ float srow[64];
    __shared__ float sbase;

    for (int s = blockIdx.x; s < nseg; s += gridDim.x) {
        const int st = ptr[s], en = ptr[s + 1];
        float4 acc = make_float4(0.f, 0.f, 0.f, 0.f);
        int j = st + rl;
        for (; j + 3 * R < en; j += 4 * R) {
            int i0 = adj[j], i1 = adj[j + R], i2 = adj[j + 2 * R], i3 = adj[j + 3 * R];
            float4 a0 = *reinterpret_cast<const float4*>(src + (size_t)i0 * C + chunk * 4);
            float4 a1 = *reinterpret_cast<const float4*>(src + (size_t)i1 * C + chunk * 4);
            float4 a2 = *reinterpret_cast<const float4*>(src + (size_t)i2 * C + chunk * 4);
            float4 a3 = *reinterpret_cast<const float4*>(src + (size_t)i3 * C + chunk * 4);
            acc.x += a0.x + a1.x + a2.x + a3.x;
            acc.y += a0.y + a1.y + a2.y + a3.y;
            acc.z += a0.z + a1.z + a2.z + a3.z;
            acc.w += a0.w + a1.w + a2.w + a3.w;
        }
        for (; j < en; j += R) {
            int i0 = adj[j];
            float4 a0 = *reinterpret_cast<const float4*>(src + (size_t)i0 * C + chunk * 4);
            acc.x += a0.x; acc.y += a0.y; acc.z += a0.z; acc.w += a0.w;
        }
        sacc[rl][chunk] = acc;
        __syncthreads();
        if (rl == 0) {
            #pragma unroll
            for (int r = 1; r < R; r++) {
                float4 o = sacc[r][chunk];
                acc.x += o.x; acc.y += o.y; acc.z += o.z; acc.w += o.w;
            }
            int deg = en - st; if (deg < 1) deg = 1;
            float inv = 1.0f / (float)deg;
            acc.x *= inv; acc.y *= inv; acc.z *= inv; acc.w *= inv;
            if (EPI == 1) {
                acc.x = fmaxf(acc.x, 0.f); acc.y = fmaxf(acc.y, 0.f);
                acc.z = fmaxf(acc.z, 0.f); acc.w = fmaxf(acc.w, 0.f);
            }
            if (EPI == 2) {
                float4 ga = *reinterpret_cast<const float4*>(bng + chunk * 4);
                float4 be = *reinterpret_cast<const float4*>(bnb + chunk * 4);
                float4 mu = *reinterpret_cast<const float4*>(bnm + chunk * 4);
                float4 va = *reinterpret_cast<const float4*>(bnv + chunk * 4);
                acc.x = (fmaxf(acc.x, 0.f) - mu.x) * rsqrtf(va.x + BN_EPS) * ga.x + be.x;
                acc.y = (fmaxf(acc.y, 0.f) - mu.y) * rsqrtf(va.y + BN_EPS) * ga.y + be.y;
                acc.z = (fmaxf(acc.z, 0.f) - mu.z) * rsqrtf(va.z + BN_EPS) * ga.z + be.z;
                acc.w = (fmaxf(acc.w, 0.f) - mu.w) * rsqrtf(va.w + BN_EPS) * ga.w + be.w;
            }
            if (EPI == 3) {
                srow[chunk * 4 + 0] = acc.x;
                srow[chunk * 4 + 1] = acc.y;
                srow[chunk * 4 + 2] = acc.z;
                srow[chunk * 4 + 3] = acc.w;
            } else {
                *reinterpret_cast<float4*>(dst + (size_t)s * C + chunk * 4) = acc;
            }
        }
        if (EPI == 3) {
            __syncthreads();
            if (tid == 0) {
                float m = -1e30f;
                #pragma unroll 8
                for (int c = 0; c < C; c++) m = fmaxf(m, srow[c]);
                float sum = 0.f;
                #pragma unroll 8
                for (int c = 0; c < C; c++) sum += __expf(srow[c] - m);
                sbase = m + logf(sum);
            }
            __syncthreads();
            if (tid < C) dst[(size_t)s * C + tid] = srow[tid] - sbase;
        }
        __syncthreads();
    }
}

// ---------------- GEMMs (row-major A[M,K] @ W[K,N] -> Out[M,N]) ----------------
// N=128, K=128. 256 threads, 64-row tile, 8 rows x 1 float4-col per thread.
template<bool RELU>
__global__ void __launch_bounds__(256)
gemm128(const float* __restrict__ A, const float* __restrict__ W,
        float* __restrict__ Out, int M) {
    __shared__ float As[64][16];
    __shared__ __align__(16) float Ws[16][128];
    const int tid = threadIdx.x;
    const int c4 = tid % 32;
    const int rg = tid / 32;
    const int row0 = blockIdx.x * 64;
    float4 acc[8];
    #pragma unroll
    for (int i = 0; i < 8; i++) acc[i] = make_float4(0.f, 0.f, 0.f, 0.f);

    for (int k0 = 0; k0 < 128; k0 += 16) {
        {
            int r = tid >> 2, cc = (tid & 3) * 4;
            int gr = row0 + r;
            float4 v = make_float4(0.f, 0.f, 0.f, 0.f);
            if (gr < M) v = *reinterpret_cast<const float4*>(A + (size_t)gr * 128 + k0 + cc);
            *reinterpret_cast<float4*>(&As[r][cc]) = v;
        }
        #pragma unroll
        for (int w = 0; w < 2; w++) {
            int idx = tid + w * 256;
            int kr = idx >> 5, cc = (idx & 31) * 4;
            *reinterpret_cast<float4*>(&Ws[kr][cc]) =
                *reinterpret_cast<const float4*>(W + (size_t)(k0 + kr) * 128 + cc);
        }
        __syncthreads();
        #pragma unroll
        for (int kk = 0; kk < 16; kk++) {
            float4 bv = *reinterpret_cast<const float4*>(&Ws[kk][c4 * 4]);
            #pragma unroll
            for (int i = 0; i < 8; i++) {
                float av = As[rg * 8 + i][kk];
                acc[i].x += av * bv.x; acc[i].y += av * bv.y;
                acc[i].z += av * bv.z; acc[i].w += av * bv.w;
            }
        }
        __syncthreads();
    }
    #pragma unroll
    for (int i = 0; i < 8; i++) {
        int gr = row0 + rg * 8 + i;
        if (gr < M) {
            float4 v = acc[i];
            if (RELU) {
                v.x = fmaxf(v.x, 0.f); v.y = fmaxf(v.y, 0.f);
                v.z = fmaxf(v.z, 0.f); v.w = fmaxf(v.w, 0.f);
            }
            *reinterpret_cast<float4*>(Out + (size_t)gr * 128 + c4 * 4) = v;
        }
    }
}

// N=40, templated K (128 or 40). 320 threads, 64-row tile, 2 rows x 1 float4-col per thread.
template<int K, bool RELU>
__global__ void __launch_bounds__(320)
gemm40(const float* __restrict__ A, const float* __restrict__ W,
       float* __restrict__ Out, int M) {
    __shared__ float As[64][16];
    __shared__ __align__(16) float Ws[16][40];
    const int tid = threadIdx.x;
    const int c4 = tid % 10;
    const int rg = tid / 10;
    const int row0 = blockIdx.x * 64;
    float4 acc[2];
    acc[0] = make_float4(0.f, 0.f, 0.f, 0.f);
    acc[1] = make_float4(0.f, 0.f, 0.f, 0.f);

    for (int k0 = 0; k0 < K; k0 += 16) {
        if (tid < 256) {
            int r = tid >> 2, cc = (tid & 3) * 4;
            int gr = row0 + r;
            float4 v = make_float4(0.f, 0.f, 0.f, 0.f);
            if (gr < M && (k0 + cc) < K)
                v = *reinterpret_cast<const float4*>(A + (size_t)gr * K + k0 + cc);
            *reinterpret_cast<float4*>(&As[r][cc]) = v;
        }
        if (tid < 160) {
            int kr = tid / 10, cc = (tid % 10) * 4;
            float4 v = make_float4(0.f, 0.f, 0.f, 0.f);
            if ((k0 + kr) < K)
                v = *reinterpret_cast<const float4*>(W + (size_t)(k0 + kr) * 40 + cc);
            *reinterpret_cast<float4*>(&Ws[kr][cc]) = v;
        }
        __syncthreads();
        #pragma unroll
        for (int kk = 0; kk < 16; kk++) {
            float4 bv = *reinterpret_cast<const float4*>(&Ws[kk][c4 * 4]);
            #pragma unroll
            for (int i = 0; i < 2; i++) {
                float av = As[rg * 2 + i][kk];
                acc[i].x += av * bv.x; acc[i].y += av * bv.y;
                acc[i].z += av * bv.z; acc[i].w += av * bv.w;
            }
        }
        __syncthreads();
    }
    #pragma unroll
    for (int i = 0; i < 2; i++) {
        int gr = row0 + rg * 2 + i;
        if (gr < M) {
            float4 v = acc[i];
            if (RELU) {
                v.x = fmaxf(v.x, 0.f); v.y = fmaxf(v.y, 0.f);
                v.z = fmaxf(v.z, 0.f); v.w = fmaxf(v.w, 0.f);
            }
            *reinterpret_cast<float4*>(Out + (size_t)gr * 40 + c4 * 4) = v;
        }
    }
}

// ---------------- host ----------------
extern "C" void kernel_launch(void* const* d_in, const int* in_sizes, int n_in,
                              void* d_out, int out_size) {
    const float* x     = (const float*)d_in[0];
    const int*   v_ids = (const int*)  d_in[1];
    const int*   e_ids = (const int*)  d_in[2];
    const float* w1a   = (const float*)d_in[3];   // (128,128) v2e
    const float* w1b   = (const float*)d_in[4];   // (128,128) e2v
    const float* w2a   = (const float*)d_in[5];   // (128,40)  v2e
    const float* w2b   = (const float*)d_in[6];   // (40,40)   e2v
    const float* bng   = (const float*)d_in[7];
    const float* bnb   = (const float*)d_in[8];
    const float* bnm   = (const float*)d_in[9];
    const float* bnv   = (const float*)d_in[10];
    float* out = (float*)d_out;
    const int nnz = in_sizes[1];

    void* p;
    cudaGetSymbolAddress(&p, g_eptr);  int* eptr  = (int*)p;
    cudaGetSymbolAddress(&p, g_vptr);  int* vptr  = (int*)p;
    cudaGetSymbolAddress(&p, g_efill); int* efill = (int*)p;
    cudaGetSymbolAddress(&p, g_vfill); int* vfill = (int*)p;
    cudaGetSymbolAddress(&p, g_eadj);  int* eadj  = (int*)p;
    cudaGetSymbolAddress(&p, g_vadj);  int* vadj  = (int*)p;
    cudaGetSymbolAddress(&p, g_ebuf);  float* ebuf  = (float*)p;
    cudaGetSymbolAddress(&p, g_ebuf2); float* ebuf2 = (float*)p;
    cudaGetSymbolAddress(&p, g_vbuf);  float* vbuf  = (float*)p;
    cudaGetSymbolAddress(&p, g_vbuf2); float* vbuf2 = (float*)p;

    // ---- CSR/CSC build (per launch; deterministic up to fp-add order) ----
    zero_counts<<<512, 256>>>(eptr, NE + 1, vptr, NV + 1);
    hist_kernel<<<2048, 256>>>(v_ids, e_ids, eptr, vptr, nnz);
    scan_two<<<2, 1024>>>(eptr, NE + 1, vptr, NV + 1);
    init_fill<<<512, 256>>>(eptr, efill, NE, vptr, vfill, NV);
    build_adj<<<2048, 256>>>(v_ids, e_ids, efill, vfill, eadj, vadj, nnz);

    // ---- layer 1 (mean commutes with linear: aggregate x first) ----
    seg_agg<128, 32, 4, 0><<<NE, 128>>>(x, eptr, eadj, ebuf, NE, nullptr, nullptr, nullptr, nullptr);
    gemm128<true ><<<(NE + 63) / 64, 256>>>(ebuf,  w1a, ebuf2, NE);   // relu(mean(x)@W1)
    gemm128<false><<<(NE + 63) / 64, 256>>>(ebuf2, w1b, ebuf,  NE);   // @W1_e2v
    seg_agg<128, 32, 4, 2><<<NV, 128>>>(ebuf, vptr, vadj, vbuf, NV, bng, bnb, bnm, bnv); // mean, relu, BN

    // ---- layer 2 ----
    gemm40<128, false><<<(NV + 63) / 64, 320>>>(vbuf, w2a, vbuf2, NV);      // h @ W2_v2e
    seg_agg<40, 10, 12, 1><<<NE, 120>>>(vbuf2, eptr, eadj, ebuf2, NE, nullptr, nullptr, nullptr, nullptr); // relu(mean)
    gemm40<40, false><<<(NE + 63) / 64, 320>>>(ebuf2, w2b, ebuf, NE);       // @ W2_e2v
    seg_agg<40, 10, 12, 3><<<NV, 120>>>(ebuf, vptr, vadj, out, NV, nullptr, nullptr, nullptr, nullptr);    // mean + log_softmax
}